// round 17
// baseline (speedup 1.0000x reference)
#include <cuda_runtime.h>
#include <cuda_fp16.h>
#include <cstdint>

#define Bsz  16
#define Cch  32
#define Himg 256
#define Wimg 256

#define TILE_H 16
#define TILE_W 32
#define HALO_W 34
#define NPIX   612            // 18 rows x 34 cols

#define THREADS 256
#define GRID_P  444           // 148 SMs x 3 CTAs
#define NTILES  2048

// smem byte offsets
#define A_OFF    0
#define WH_OFF   (NPIX * 64)             // 39168
#define BIAS_OFF (WH_OFF + 9 * 2048)     // 57600 (16 half2 = 64B)
#define GATE_OFF (BIAS_OFF + 128)        // 2 slots x 16 half2
#define SMEM_BYTES (GATE_OFF + 256)      // 57984 -> 3 CTAs/SM

// h scratch: per pixel 32 fp16 = 16 uint32, single plane. 64 MB.
#define HPIX   (16u * 65536u)            // Bsz*Himg*Wimg
__device__ uint32_t g_h[(size_t)HPIX * 16u];

// pre-converted weight smem images (fp16, swizzled layout), 18432 B each
__device__ uint4 g_w16[2 * 1152];

// pass-1 tile-row completion counters: [b][ty], reaches 8 when row done
__device__ int g_rowcnt[Bsz * 16];

// ---------------- helpers ----------------
__device__ __forceinline__ uint32_t smem_u32(const void* p) {
    uint32_t a;
    asm("{ .reg .u64 t; cvta.to.shared.u64 t, %1; cvt.u32.u64 %0, t; }"
        : "=r"(a) : "l"(p));
    return a;
}
__device__ __forceinline__ void ldmx4(uint32_t* d, uint32_t a) {
    asm volatile("ldmatrix.sync.aligned.m8n8.x4.shared.b16 {%0,%1,%2,%3}, [%4];"
                 : "=r"(d[0]), "=r"(d[1]), "=r"(d[2]), "=r"(d[3]) : "r"(a));
}
__device__ __forceinline__ void ldmx4t(uint32_t* d, uint32_t a) {
    asm volatile("ldmatrix.sync.aligned.m8n8.x4.trans.shared.b16 {%0,%1,%2,%3}, [%4];"
                 : "=r"(d[0]), "=r"(d[1]), "=r"(d[2]), "=r"(d[3]) : "r"(a));
}
// fp16-accumulate HMMA: C/D are 2 packed half2 regs
__device__ __forceinline__ void mma16816h(uint32_t* c, const uint32_t* a, const uint32_t* b) {
    asm volatile("mma.sync.aligned.m16n8k16.row.col.f16.f16.f16.f16 "
                 "{%0,%1}, {%2,%3,%4,%5}, {%6,%7}, {%0,%1};"
                 : "+r"(c[0]), "+r"(c[1])
                 : "r"(a[0]), "r"(a[1]), "r"(a[2]), "r"(a[3]),
                   "r"(b[0]), "r"(b[1]));
}
// pack two fp32 -> half2 (lo = first arg)
__device__ __forceinline__ uint32_t cvt2(float lo, float hi) {
    uint32_t d;
    asm("cvt.rn.f16x2.f32 %0, %1, %2;" : "=r"(d) : "f"(hi), "f"(lo));
    return d;
}
// cp.async 16B with zero-fill when bytes==0
__device__ __forceinline__ void cpa16(uint32_t dst, const void* src, uint32_t bytes) {
    asm volatile("cp.async.cg.shared.global [%0], [%1], 16, %2;"
                 :: "r"(dst), "l"(src), "r"(bytes) : "memory");
}
__device__ __forceinline__ void cpa_commit() {
    asm volatile("cp.async.commit_group;" ::: "memory");
}
__device__ __forceinline__ void cpa_waitall() {
    asm volatile("cp.async.wait_group 0;" ::: "memory");
}

// A-tile: pixel p -> 64B (4 granules of 16B = 8 ci fp16).
__device__ __forceinline__ uint32_t a_byte(int p, int kc) {
    return (uint32_t)(p * 64 + (((kc + p + (p >> 2)) & 3) << 4));
}
// W-tile within one tap: row ci (64B = 32 co fp16), granule nb = co/8
__device__ __forceinline__ uint32_t w_byte(int ci, int nb) {
    return (uint32_t)(ci * 64 + (((nb + ((ci >> 1) & 3)) & 3) << 4));
}

// ---------------- weight prep kernel (also zeroes row counters) ----------------
__global__ void prep_weights(const float* __restrict__ w1,
                             const float* __restrict__ w2)
{
    if (blockIdx.x == 0 && threadIdx.x < Bsz * 16)
        g_rowcnt[threadIdx.x] = 0;
    int i = blockIdx.x * 256 + threadIdx.x;      // 0 .. 18431
    if (i >= 2 * 9216) return;
    int sel = i >= 9216;
    int j   = i - sel * 9216;
    int co  = j / 288;
    int rem = j - co * 288;
    int ci  = rem / 9;
    int tap = rem - ci * 9;
    uint32_t byte = tap * 2048 + w_byte(ci, co >> 3) + ((co & 7) << 1);
    const float* w = sel ? w2 : w1;
    char* dst = (char*)g_w16 + sel * 18432 + byte;
    *(__half*)dst = __float2half(w[j]);
}

// ---------------- tile fill helpers ----------------
__device__ __forceinline__ void fill_p1(char* sm, const float* __restrict__ x,
                                        int b, int y0, int x0, int tid)
{
    {
        const int cp = tid >> 4;
        const int j  = tid & 15;
        const int kc  = cp >> 2;
        const int sub = (cp & 3) << 2;
        const float* xc = &x[((size_t)b * Cch + cp * 2) * (Himg * Wimg)];
        #pragma unroll
        for (int k = 0; k < 9; k++) {
            const int rem = j + (k << 4);       // 0..143
            const int r   = rem >> 3;
            const int q   = rem & 7;
            const int gy  = y0 - 1 + r;
            const int p0  = r * HALO_W + 1 + q * 4;
            float4 va = make_float4(0.f, 0.f, 0.f, 0.f), vb = va;
            if ((unsigned)gy < (unsigned)Himg) {
                const float* src = xc + gy * Wimg + x0 + q * 4;
                va = *(const float4*)src;
                vb = *(const float4*)(src + Himg * Wimg);
            }
            *(uint32_t*)(sm + A_OFF + a_byte(p0,     kc) + sub) = cvt2(va.x, vb.x);
            *(uint32_t*)(sm + A_OFF + a_byte(p0 + 1, kc) + sub) = cvt2(va.y, vb.y);
            *(uint32_t*)(sm + A_OFF + a_byte(p0 + 2, kc) + sub) = cvt2(va.z, vb.z);
            *(uint32_t*)(sm + A_OFF + a_byte(p0 + 3, kc) + sub) = cvt2(va.w, vb.w);
        }
    }
    for (int i = tid; i < 16 * 18 * 2; i += THREADS) {
        int cp  = i / 36;
        int rem = i - cp * 36;
        int r   = rem >> 1;
        int e   = rem & 1;
        int gy  = y0 - 1 + r;
        int gx  = x0 - 1 + e * 33;
        int p   = r * HALO_W + e * 33;
        float va = 0.f, vb = 0.f;
        if ((unsigned)gy < (unsigned)Himg && (unsigned)gx < (unsigned)Wimg) {
            const float* src = &x[(((size_t)b * Cch + cp * 2) * Himg + gy) * Wimg + gx];
            va = src[0];
            vb = src[Himg * Wimg];
        }
        *(uint32_t*)(sm + A_OFF + a_byte(p, cp >> 2) + ((cp & 3) << 2)) = cvt2(va, vb);
    }
}

__device__ __forceinline__ void prefetch_p1(const float* __restrict__ x,
                                            int b, int y0, int x0, int tid)
{
    const int cp = tid >> 4;
    const int j  = tid & 15;
    const float* xc = &x[((size_t)b * Cch + cp * 2) * (Himg * Wimg)];
    #pragma unroll
    for (int k = 0; k < 9; k++) {
        const int rem = j + (k << 4);
        const int r   = rem >> 3;
        const int q   = rem & 7;
        const int gy  = y0 - 1 + r;
        if ((unsigned)gy < (unsigned)Himg) {
            const float* src = xc + gy * Wimg + x0 + q * 4;
            asm volatile("prefetch.global.L2 [%0];" :: "l"(src));
            asm volatile("prefetch.global.L2 [%0];" :: "l"(src + Himg * Wimg));
        }
    }
}

// issue cp.async fills for pass2 (no wait)
__device__ __forceinline__ void issue_p2(uint32_t smb, int b, int y0, int x0, int tid)
{
    const uint4* gh4 = (const uint4*)g_h;
    for (int i = tid; i < NPIX * 4; i += THREADS) {
        int p = i >> 2, chunk = i & 3;
        int gy = y0 - 1 + p / HALO_W;
        int gx = x0 - 1 + p % HALO_W;
        bool valid = (unsigned)gy < (unsigned)Himg && (unsigned)gx < (unsigned)Wimg;
        uint32_t pix = valid ? (((uint32_t)b << 16) + gy * 256 + gx) : 0u;
        cpa16(smb + A_OFF + a_byte(p, chunk),
              gh4 + (size_t)pix * 4 + chunk,
              valid ? 16u : 0u);
    }
    cpa_commit();
}

// wait for the <=3 producer rows of tile (b, ty) — every thread acquires
__device__ __forceinline__ void wait_deps(int b, int y0)
{
    const int ty = y0 >> 4;
    const int lo = (ty > 0) ? ty - 1 : 0;
    const int hi = (ty < 15) ? ty + 1 : 15;
    #pragma unroll 1
    for (int r = lo; r <= hi; r++) {
        const int* p = &g_rowcnt[(b << 4) + r];
        int v;
        while (true) {
            asm volatile("ld.acquire.gpu.global.b32 %0, [%1];" : "=r"(v) : "l"(p));
            if (v >= 8) break;
            __nanosleep(128);
        }
    }
}

// ---------------- fused main kernel (persistent, both passes) ----------------
__global__ __launch_bounds__(THREADS, 3)
void conv_fused(const float* __restrict__ x,
                const float* __restrict__ b1,
                const float* __restrict__ b2,
                const float* __restrict__ gate,
                float* __restrict__ out)
{
    extern __shared__ char sm[];
    const uint32_t smb = smem_u32(sm);
    const int tid = threadIdx.x;

    const int wid  = tid >> 5;
    const int lane = tid & 31;
    const int r0   = (wid >> 1) * 4;
    const int mbw  = wid & 1;
    const int lm   = lane & 15;
    const int ksel = (lane >> 4) & 1;
    const int grp  = lane >> 2, tig = lane & 3;
    const __half2 hz = __float2half2_rn(0.0f);

    // ================= PHASE 1 =================
    {
        const uint4* wsrc = g_w16;
        uint4* wdst = (uint4*)(sm + WH_OFF);
        #pragma unroll
        for (int k = 0; k < 5; k++) {
            int i = tid + k * THREADS;
            if (i < 1152) wdst[i] = wsrc[i];
        }
        if (tid < 16)
            ((__half2*)(sm + BIAS_OFF))[tid] =
                __floats2half2_rn(b1[2 * tid], b1[2 * tid + 1]);
    }

    int tile = blockIdx.x;
    {
        const int b  = tile >> 7;
        const int y0 = ((tile >> 3) & 15) * TILE_H;
        const int x0 = (tile & 7) * TILE_W;
        if (tid < 16) {
            float g0 = fmaxf(gate[b * 32 + 2 * tid],     0.0f);
            float g1 = fmaxf(gate[b * 32 + 2 * tid + 1], 0.0f);
            ((__half2*)(sm + GATE_OFF))[tid] = __floats2half2_rn(g0, g1);
        }
        fill_p1(sm, x, b, y0, x0, tid);
    }
    __syncthreads();

    int it = 0;
    while (tile < NTILES) {
        const int b  = tile >> 7;
        const int y0 = ((tile >> 3) & 15) * TILE_H;
        const int x0 = (tile & 7) * TILE_W;
        const int sl = it & 1;

        uint32_t acc[4][4][2];
        #pragma unroll
        for (int rr = 0; rr < 4; rr++)
            #pragma unroll
            for (int nb = 0; nb < 4; nb++) {
                acc[rr][nb][0] = 0u;
                acc[rr][nb][1] = 0u;
            }

        #pragma unroll
        for (int kb = 0; kb < 2; kb++) {
            const int krow = kb * 16 + lm;
            const uint32_t wo0 = smb + WH_OFF + w_byte(krow, ksel);
            const uint32_t wo1 = smb + WH_OFF + w_byte(krow, 2 + ksel);
            #pragma unroll
            for (int dx = 0; dx < 3; dx++) {
                uint32_t Bh[3][2][4];
                #pragma unroll
                for (int dy = 0; dy < 3; dy++) {
                    const uint32_t tb = (dy * 3 + dx) * 2048;
                    ldmx4t(Bh[dy][0], wo0 + tb);
                    ldmx4t(Bh[dy][1], wo1 + tb);
                }
                #pragma unroll
                for (int t = 0; t < 6; t++) {
                    uint32_t Ah[4];
                    const int p = (r0 + t) * HALO_W + dx + mbw * 16 + lm;
                    ldmx4(Ah, smb + A_OFF + a_byte(p, kb * 2 + ksel));
                    #pragma unroll
                    for (int dy = 0; dy < 3; dy++) {
                        const int rr = t - dy;
                        if (rr >= 0 && rr < 4) {
                            #pragma unroll
                            for (int np = 0; np < 2; np++) {
                                mma16816h(acc[rr][np * 2],     Ah, &Bh[dy][np][0]);
                                mma16816h(acc[rr][np * 2 + 1], Ah, &Bh[dy][np][2]);
                            }
                        }
                    }
                }
            }
        }
        __syncthreads();

        const int ntile = tile + GRID_P;
        const bool hasn = ntile < NTILES;
        int nb_ = 0, ny0 = 0, nx0 = 0;
        if (hasn) {
            nb_ = ntile >> 7;
            ny0 = ((ntile >> 3) & 15) * TILE_H;
            nx0 = (ntile & 7) * TILE_W;
            if (tid < 16) {
                float g0 = fmaxf(gate[nb_ * 32 + 2 * tid],     0.0f);
                float g1 = fmaxf(gate[nb_ * 32 + 2 * tid + 1], 0.0f);
                ((__half2*)(sm + GATE_OFF))[((it + 1) & 1) * 16 + tid] =
                    __floats2half2_rn(g0, g1);
            }
            prefetch_p1(x, nb_, ny0, nx0, tid);
        }

        // epilogue -> g_h
        {
            const __half2* bs2 = (const __half2*)(sm + BIAS_OFF);
            const __half2* gs2 = (const __half2*)(sm + GATE_OFF) + sl * 16;
            __half2 b2r[4], g2r[4];
            #pragma unroll
            for (int nb = 0; nb < 4; nb++) {
                b2r[nb] = bs2[nb * 4 + tig];
                g2r[nb] = gs2[nb * 4 + tig];
            }
            #pragma unroll
            for (int rr = 0; rr < 4; rr++) {
                const int y = y0 + r0 + rr;
                #pragma unroll
                for (int half = 0; half < 2; half++) {
                    const int xg = x0 + mbw * 16 + grp + half * 8;
                    const uint32_t hbase =
                        ((((uint32_t)b << 16) + ((uint32_t)y << 8) + xg) << 4);
                    #pragma unroll
                    for (int nb = 0; nb < 4; nb++) {
                        __half2 a2 = *reinterpret_cast<__half2*>(&acc[rr][nb][half]);
                        __half2 t2 = __hmul2(g2r[nb], __hmax2(__hadd2(a2, b2r[nb]), hz));
                        const int co = nb * 8 + tig * 2;
                        g_h[hbase + (co >> 1)] = *reinterpret_cast<uint32_t*>(&t2);
                    }
                }
            }
        }

        if (hasn) fill_p1(sm, x, nb_, ny0, nx0, tid);
        __threadfence();                 // order this thread's g_h stores
        __syncthreads();                 // all threads fenced
        if (tid == 0)
            asm volatile("red.release.gpu.global.add.s32 [%0], 1;"
                         :: "l"(&g_rowcnt[(b << 4) + (y0 >> 4)]) : "memory");

        tile = ntile;
        it++;
    }

    // ================= PHASE 2 =================
    {
        const uint4* wsrc = g_w16 + 1152;
        uint4* wdst = (uint4*)(sm + WH_OFF);
        #pragma unroll
        for (int k = 0; k < 5; k++) {
            int i = tid + k * THREADS;
            if (i < 1152) wdst[i] = wsrc[i];
        }
        if (tid < 16)
            ((__half2*)(sm + BIAS_OFF))[tid] =
                __floats2half2_rn(b2[2 * tid], b2[2 * tid + 1]);
    }

    tile = blockIdx.x;
    {
        const int b  = tile >> 7;
        const int y0 = ((tile >> 3) & 15) * TILE_H;
        const int x0 = (tile & 7) * TILE_W;
        if (tid < 16) {
            float g0 = fmaxf(gate[b * 32 + 2 * tid],     0.0f);
            float g1 = fmaxf(gate[b * 32 + 2 * tid + 1], 0.0f);
            ((__half2*)(sm + GATE_OFF))[tid] = __floats2half2_rn(g0, g1);
        }
        wait_deps(b, y0);
        issue_p2(smb, b, y0, x0, tid);
        cpa_waitall();
    }
    __syncthreads();

    it = 0;
    while (tile < NTILES) {
        const int b  = tile >> 7;
        const int y0 = ((tile >> 3) & 15) * TILE_H;
        const int x0 = (tile & 7) * TILE_W;
        const int sl = it & 1;

        uint32_t acc[4][4][2];
        #pragma unroll
        for (int rr = 0; rr < 4; rr++)
            #pragma unroll
            for (int nb = 0; nb < 4; nb++) {
                acc[rr][nb][0] = 0u;
                acc[rr][nb][1] = 0u;
            }

        #pragma unroll
        for (int kb = 0; kb < 2; kb++) {
            const int krow = kb * 16 + lm;
            const uint32_t wo0 = smb + WH_OFF + w_byte(krow, ksel);
            const uint32_t wo1 = smb + WH_OFF + w_byte(krow, 2 + ksel);
            #pragma unroll
            for (int dx = 0; dx < 3; dx++) {
                uint32_t Bh[3][2][4];
                #pragma unroll
                for (int dy = 0; dy < 3; dy++) {
                    const uint32_t tb = (dy * 3 + dx) * 2048;
                    ldmx4t(Bh[dy][0], wo0 + tb);
                    ldmx4t(Bh[dy][1], wo1 + tb);
                }
                #pragma unroll
                for (int t = 0; t < 6; t++) {
                    uint32_t Ah[4];
                    const int p = (r0 + t) * HALO_W + dx + mbw * 16 + lm;
                    ldmx4(Ah, smb + A_OFF + a_byte(p, kb * 2 + ksel));
                    #pragma unroll
                    for (int dy = 0; dy < 3; dy++) {
                        const int rr = t - dy;
                        if (rr >= 0 && rr < 4) {
                            #pragma unroll
                            for (int np = 0; np < 2; np++) {
                                mma16816h(acc[rr][np * 2],     Ah, &Bh[dy][np][0]);
                                mma16816h(acc[rr][np * 2 + 1], Ah, &Bh[dy][np][2]);
                            }
                        }
                    }
                }
            }
        }
        __syncthreads();

        const int ntile = tile + GRID_P;
        const bool hasn = ntile < NTILES;
        if (hasn) {
            const int nb_ = ntile >> 7;
            const int ny0 = ((ntile >> 3) & 15) * TILE_H;
            const int nx0 = (ntile & 7) * TILE_W;
            if (tid < 16) {
                float g0 = fmaxf(gate[nb_ * 32 + 2 * tid],     0.0f);
                float g1 = fmaxf(gate[nb_ * 32 + 2 * tid + 1], 0.0f);
                ((__half2*)(sm + GATE_OFF))[((it + 1) & 1) * 16 + tid] =
                    __floats2half2_rn(g0, g1);
            }
            wait_deps(nb_, ny0);
            issue_p2(smb, nb_, ny0, nx0, tid);
        }

        // epilogue -> out (exact fp32 residual)
        {
            const __half2* bs2 = (const __half2*)(sm + BIAS_OFF);
            const __half2* gs2 = (const __half2*)(sm + GATE_OFF) + sl * 16;
            __half2 b2r[4], g2r[4];
            #pragma unroll
            for (int nb = 0; nb < 4; nb++) {
                b2r[nb] = bs2[nb * 4 + tig];
                g2r[nb] = gs2[nb * 4 + tig];
            }
            #pragma unroll
            for (int rr = 0; rr < 4; rr++) {
                const int y = y0 + r0 + rr;
                #pragma unroll
                for (int half = 0; half < 2; half++) {
                    const int xg = x0 + mbw * 16 + grp + half * 8;
                    const uint32_t obase =
                        ((uint32_t)b << 21) + ((uint32_t)y << 8) + xg;
                    #pragma unroll
                    for (int nb = 0; nb < 4; nb++) {
                        __half2 a2 = *reinterpret_cast<__half2*>(&acc[rr][nb][half]);
                        __half2 t2 = __hmul2(g2r[nb], __hmax2(__hadd2(a2, b2r[nb]), hz));
                        const int co = nb * 8 + tig * 2;
                        float2 f = __half22float2(t2);
                        uint32_t i0 = obase + (uint32_t)co * 65536u;
                        out[i0]          = f.x + x[i0];
                        out[i0 + 65536u] = f.y + x[i0 + 65536u];
                    }
                }
            }
        }

        if (hasn) cpa_waitall();
        __syncthreads();

        tile = ntile;
        it++;
    }
}

extern "C" void kernel_launch(void* const* d_in, const int* in_sizes, int n_in,
                              void* d_out, int out_size)
{
    const float* x    = (const float*)d_in[0];
    const float* gate = (const float*)d_in[1];
    const float* w1   = (const float*)d_in[2];
    const float* b1   = (const float*)d_in[3];
    const float* w2   = (const float*)d_in[4];
    const float* b2   = (const float*)d_in[5];
    float*       out  = (float*)d_out;
    (void)in_sizes; (void)n_in; (void)out_size;

    cudaFuncSetAttribute(conv_fused,
                         cudaFuncAttributeMaxDynamicSharedMemorySize, SMEM_BYTES);

    prep_weights<<<72, 256>>>(w1, w2);
    conv_fused<<<GRID_P, THREADS, SMEM_BYTES>>>(x, b1, b2, gate, out);
}